// round 6
// baseline (speedup 1.0000x reference)
#include <cuda_runtime.h>
#include <cstdint>

#define CTC_V  128
#define NEG2   (-1.0e30f)
#define KS     8                  // steps per block
#define TMAX   1024
#define BMAX   64
#define PPAD   258
#define BLKMAX ((TMAX + KS - 1) / KS)   // 128

// Scratch
__device__ float  g_probs[TMAX * BMAX * CTC_V];
__device__ float  g_blank[BMAX * TMAX];
__device__ float2 g_final[BMAX * PPAD];
__device__ float4 g_hand[BMAX * BLKMAX * KS * 2];   // [b][blk][j<8][2]

__device__ __forceinline__ float ex2(float x) {
    float y; asm("ex2.approx.ftz.f32 %0, %1;" : "=f"(y) : "f"(x)); return y;
}
__device__ __forceinline__ float lg2(float x) {
    float y; asm("lg2.approx.ftz.f32 %0, %1;" : "=f"(y) : "f"(x)); return y;
}
__device__ __forceinline__ float4 ldcg4(const float4* p) {
    float4 v;
    asm volatile("ld.global.cg.v4.f32 {%0,%1,%2,%3}, [%4];"
                 : "=f"(v.x), "=f"(v.y), "=f"(v.z), "=f"(v.w) : "l"(p));
    return v;
}
__device__ __forceinline__ void stcg4(float4* p, float4 v) {
    asm volatile("st.global.cg.v4.f32 [%0], {%1,%2,%3,%4};"
                 :: "l"(p), "f"(v.x), "f"(v.y), "f"(v.z), "f"(v.w) : "memory");
}

// ---------------------------------------------------------------------------
// Kernel 1: log2-softmax over V=128 per (t,b) row; also compact blank stream.
// ---------------------------------------------------------------------------
__global__ void softmax_k(const float* __restrict__ acts, int rows, int T, int B) {
    int gw   = (blockIdx.x * blockDim.x + threadIdx.x) >> 5;
    int lane = threadIdx.x & 31;
    if (gw >= rows) return;
    const float L2E = 1.4426950408889634f;
    float4 v = reinterpret_cast<const float4*>(acts)[(size_t)gw * 32 + lane];
    float x0 = v.x * L2E, x1 = v.y * L2E, x2 = v.z * L2E, x3 = v.w * L2E;
    float m = fmaxf(fmaxf(x0, x1), fmaxf(x2, x3));
#pragma unroll
    for (int o = 16; o; o >>= 1) m = fmaxf(m, __shfl_xor_sync(0xffffffffu, m, o));
    float ssum = ex2(x0 - m) + ex2(x1 - m) + ex2(x2 - m) + ex2(x3 - m);
#pragma unroll
    for (int o = 16; o; o >>= 1) ssum += __shfl_xor_sync(0xffffffffu, ssum, o);
    float ls = lg2(ssum) + m;
    reinterpret_cast<float4*>(g_probs)[(size_t)gw * 32 + lane] =
        make_float4(x0 - ls, x1 - ls, x2 - ls, x3 - ls);
    if (lane == 0) {
        int t = gw / B, b = gw - t * B;
        g_blank[b * T + t] = x0 - ls;
    }
}

// ---------------------------------------------------------------------------
// Kernel 2: alpha recursion. 2 CTAs per batch (left/right states), 2 pairs
// per thread, KS steps per barrier, tagged global handoff left->right.
// ---------------------------------------------------------------------------
__global__ __launch_bounds__(96, 1) void ctc_alpha_k(
    const int* __restrict__ labels, const int* __restrict__ act_lens,
    const int* __restrict__ label_lens, int T, int B, int L)
{
    __shared__ __align__(16) float2 sh[2][160];

    const int V = CTC_V;
    const int cta   = blockIdx.x;
    const int b     = cta >> 1;
    const bool right = (cta & 1);
    const int P  = L + 1;
    const int PL = ((P + 1) / 2) & ~1;          // left pair count (even)
    const int base = right ? PL : 0;
    const int Pcta = right ? (P - PL) : PL;

    const int tid  = threadIdx.x;
    const int lane = tid & 31, w = tid >> 5;

    int Tlen = act_lens[b];
    if (Tlen > T) Tlen = T;
    if (Tlen < 1) Tlen = 1;
    const int NB = (Tlen - 1 + KS - 1) / KS;

    const int qA = w * 48 + 2 * (lane - KS);    // local even pair idx (may be <0)
    const int pA = base + qA, pB = pA + 1;
    const bool in0A = ((unsigned)pA < (unsigned)P);
    const bool in1A = ((unsigned)pA < (unsigned)L);
    const bool in0B = ((unsigned)pB < (unsigned)P);
    const bool in1B = ((unsigned)pB < (unsigned)L);
    const int labA = in1A ? labels[b * L + pA] : 0;
    const int labB = in1B ? labels[b * L + pB] : 0;
    const bool alA = in1A && (pA >= 1) && (labA != labels[b * L + pA - 1]);
    const bool alB = in1B && (labB != labA);    // pB-1 == pA

    const float* __restrict__ plA = g_probs + (size_t)b * V + labA;
    const float* __restrict__ plB = g_probs + (size_t)b * V + labB;
    const float* __restrict__ pb  = g_blank + (size_t)b * T;
    const size_t rstr = (size_t)B * V;

    const bool useful = (lane >= KS) && (qA < Pcta);     // qA>=0 implied
    const bool haloG  = right && (w == 0) && (lane < KS);
    const bool pub    = (!right) && (lane >= KS) && (qA >= PL - 2 * KS) && (qA < PL);

    // init alpha(t=0) into sh[0]
    if (useful) {
        float c0 = NEG2, c1 = NEG2;
        if (pA == 0) { c0 = __ldg(pb); c1 = in1A ? __ldg(plA) : NEG2; }
        sh[0][qA]     = make_float2(c0, c1);
        sh[0][qA + 1] = make_float2(NEG2, NEG2);   // pB>=1 always
    }

    // emits for block 0 (t = 1..KS)
    float eb[KS], eA[KS], eB[KS];
#pragma unroll
    for (int j = 0; j < KS; ++j) {
        int t = 1 + j; bool ok = (t < Tlen);
        eb[j] = ok ? __ldg(pb + t) : 0.0f;
        eA[j] = ok ? __ldg(plA + (size_t)t * rstr) : 0.0f;
        eB[j] = ok ? __ldg(plB + (size_t)t * rstr) : 0.0f;
    }
    __syncthreads();

    float4* hslot0 = g_hand + ((size_t)b * BLKMAX * KS) * 2;
    float4 pf0 = make_float4(0, 0, 0, 0), pf1 = pf0;
    if (haloG && NB > 1) {                 // prefetch slot 0 (tag 1) for blk 1
        pf0 = ldcg4(hslot0 + lane * 2);
        pf1 = ldcg4(hslot0 + lane * 2 + 1);
    }

    float cA0 = NEG2, cA1 = NEG2, cB0 = NEG2, cB1 = NEG2;

    for (int blk = 0; blk < NB; ++blk) {
        // ---- load state at time blk*KS ----
        if (haloG && blk > 0) {
            const float4* sp = hslot0 + ((size_t)(blk - 1) * KS + lane) * 2;
            while (__float_as_int(pf0.z) != blk || __float_as_int(pf1.z) != blk) {
                pf0 = ldcg4(sp); pf1 = ldcg4(sp + 1);
            }
            cA0 = pf0.x; cA1 = pf0.y; cB0 = pf1.x; cB1 = pf1.y;
        } else {
            int qq = qA < 0 ? 0 : qA;
            float4 v = *reinterpret_cast<float4*>(&sh[blk & 1][qq]);
            bool okA = (qA >= 0) && (qA < Pcta);
            bool okB = (qA + 1 >= 0) && (qA + 1 < Pcta);
            cA0 = okA ? v.x : NEG2; cA1 = okA ? v.y : NEG2;
            cB0 = okB ? v.z : NEG2; cB1 = okB ? v.w : NEG2;
        }
        // prefetch handoff for next block (slot blk, tag blk+1)
        if (haloG && (blk + 1) < NB) {
            const float4* sp = hslot0 + ((size_t)blk * KS + lane) * 2;
            pf0 = ldcg4(sp); pf1 = ldcg4(sp + 1);
        }
        // prefetch emits for next block
        float nb_[KS], nA_[KS], nB_[KS];
        {
            int tb = (blk + 1) * KS + 1;
#pragma unroll
            for (int j = 0; j < KS; ++j) {
                int t = tb + j; bool ok = (t < Tlen);
                nb_[j] = ok ? __ldg(pb + t) : 0.0f;
                nA_[j] = ok ? __ldg(plA + (size_t)t * rstr) : 0.0f;
                nB_[j] = ok ? __ldg(plB + (size_t)t * rstr) : 0.0f;
            }
        }

        // ---- KS recursion steps ----
#pragma unroll
        for (int j = 0; j < KS; ++j) {
            int t = blk * KS + 1 + j;
            float z = __shfl_up_sync(0xffffffffu, cB1, 1);   // c1 of pair pA-1
            // pair A
            float m0 = fmaxf(cA0, z);
            float s0 = m0 + lg2(1.0f + ex2(fminf(cA0, z) - m0)) + eb[j];
            float qv = alA ? z : NEG2;
            float h  = fmaxf(cA1, cA0), lo = fminf(cA1, cA0);
            float m1 = fmaxf(h, qv),  l2v = fminf(h, qv);
            float s1 = m1 + lg2(1.0f + ex2(lo - m1) + ex2(l2v - m1)) + eA[j];
            // pair B (uses pre-update cA0/cA1)
            float m0b = fmaxf(cB0, cA1);
            float s0b = m0b + lg2(1.0f + ex2(fminf(cB0, cA1) - m0b)) + eb[j];
            float qb  = alB ? cA1 : NEG2;
            float hb  = fmaxf(cB1, cB0), lob = fminf(cB1, cB0);
            float m1b = fmaxf(hb, qb),  l2b = fminf(hb, qb);
            float s1b = m1b + lg2(1.0f + ex2(lob - m1b) + ex2(l2b - m1b)) + eB[j];
            bool upd = (t < Tlen);
            cA0 = (upd && in0A) ? s0  : cA0;
            cA1 = (upd && in1A) ? s1  : cA1;
            cB0 = (upd && in0B) ? s0b : cB0;
            cB1 = (upd && in1B) ? s1b : cB1;
        }

        // ---- store state, publish boundary ----
        if (useful)
            *reinterpret_cast<float4*>(&sh[(blk + 1) & 1][qA]) =
                make_float4(cA0, cA1, cB0, cB1);
        if (pub) {
            int jj = (qA - (PL - 2 * KS)) >> 1;           // 0..7
            float tg = __int_as_float(blk + 1);
            float4* sp = hslot0 + ((size_t)blk * KS + jj) * 2;
            stcg4(sp,     make_float4(cA0, cA1, tg, 0.f));
            stcg4(sp + 1, make_float4(cB0, cB1, tg, 0.f));
        }
        __syncthreads();

#pragma unroll
        for (int j = 0; j < KS; ++j) { eb[j] = nb_[j]; eA[j] = nA_[j]; eB[j] = nB_[j]; }
    }

    // final alpha -> global
    if (useful) {
        float4 v = *reinterpret_cast<float4*>(&sh[NB & 1][qA]);
        g_final[(size_t)b * PPAD + base + qA] = make_float2(v.x, v.y);
        if (qA + 1 < Pcta)
            g_final[(size_t)b * PPAD + base + qA + 1] = make_float2(v.z, v.w);
    }
}

// ---------------------------------------------------------------------------
// Kernel 3: per-example cost + deterministic sum.
// ---------------------------------------------------------------------------
__global__ void cost_k(float* out, const int* __restrict__ label_lens, int B, int L) {
    int P = L + 1;
    float sum = 0.0f;
    for (int i = threadIdx.x; i < B; i += 32) {
        int e = label_lens[i]; if (e > P - 1) e = P - 1;
        float2 f0 = g_final[(size_t)i * PPAD + e];
        float a0 = f0.x;
        float a1 = (e >= 1) ? g_final[(size_t)i * PPAD + e - 1].y : NEG2;
        float m = fmaxf(a0, a1);
        sum += -(m + lg2(ex2(a0 - m) + ex2(a1 - m))) * 0.69314718055994530942f;
    }
#pragma unroll
    for (int o = 16; o; o >>= 1) sum += __shfl_xor_sync(0xffffffffu, sum, o);
    if (threadIdx.x == 0) *out = sum;
}

// ---------------------------------------------------------------------------
extern "C" void kernel_launch(void* const* d_in, const int* in_sizes, int n_in,
                              void* d_out, int out_size)
{
    const float* acts      = (const float*)d_in[0];
    const int*   labels    = (const int*)d_in[1];
    const int*   act_lens  = (const int*)d_in[2];
    const int*   label_len = (const int*)d_in[3];

    int B = in_sizes[2];
    int L = in_sizes[1] / B;
    int V = CTC_V;
    int T = in_sizes[0] / (B * V);

    int rows = T * B;
    softmax_k<<<(rows + 7) / 8, 256>>>(acts, rows, T, B);

    ctc_alpha_k<<<2 * B, 96>>>(labels, act_lens, label_len, T, B, L);

    cost_k<<<1, 32>>>((float*)d_out, label_len, B, L);
}